// round 10
// baseline (speedup 1.0000x reference)
#include <cuda_runtime.h>
#include <math.h>

#define BB 4
#define NN 3000
#define CC 21
#define BN (BB*NN)

#define NGROUPS (BB*(CC-1))            // 80
#define THREADS 256
#define PREP_BLOCKS ((BN + THREADS - 1) / THREADS)   // 47
#define NBLK (NGROUPS + PREP_BLOCKS)   // 127
#define TILE 256
#define NTILES ((NN + TILE - 1) / TILE)   // 12
#define MAXM  320
#define WMAX  10

// ---------------------------------------------------------------------------
// out layout (float32): [rounded BN*4][sigmoid BN][boxes BN*4][probs BN*C][keep BN]
// ---------------------------------------------------------------------------

// sbuf (24576 B) overlays:
//   gather/prep: logit staging, up to 256*21 floats (21504 B)
//   group NMS:   tlbr f4 [0,5120) | area f [5120,6400) | sidx i32 [6400,7680)
//                keptw u32 [7680,7720)
//   fallback:    keys u64 [0,24576) (3072 entries)
__shared__ unsigned char      sbuf[24576];
__shared__ unsigned int       maskbuf[MAXM * WMAX];   // 12800 B
__shared__ unsigned long long keysbuf[MAXM];          // 2560 B
__shared__ int s_count;

__device__ __forceinline__ void load_box(const float* __restrict__ nms_reg,
                                         const float* __restrict__ rcnn_reg,
                                         float red, int gidx, float4* box)
{
    float4 r  = ((const float4*)nms_reg)[gidx];
    float4 rg = ((const float4*)rcnn_reg)[gidx];
    float q0 = __fdiv_rn(floorf(__fmul_rn(r.x, red)), red);
    float q1 = __fdiv_rn(floorf(__fmul_rn(r.y, red)), red);
    float q2 = __fdiv_rn(ceilf(__fmul_rn(r.z, red)), red);
    float q3 = __fdiv_rn(ceilf(__fmul_rn(r.w, red)), red);
    box->x = __fadd_rn(rg.x, q0);
    box->y = __fadd_rn(rg.y, q1);
    box->z = __fadd_rn(rg.z, q2);
    box->w = __fadd_rn(rg.w, q3);
}

__global__ void __launch_bounds__(THREADS)
fused_kernel(const float* __restrict__ nms_reg,
             const float* __restrict__ nms_cls,
             const float* __restrict__ rcnn_reg,
             const float* __restrict__ rcnn_cls,
             const unsigned int* __restrict__ red_raw,
             float* __restrict__ out)
{
    int tid  = threadIdx.x;
    int lane = tid & 31;
    int bid  = blockIdx.x;

    unsigned int wr = red_raw[0];
    float red = (wr < 0x10000u) ? (float)wr : __uint_as_float(wr);

    float* o_keep = out + BN * 9 + BN * CC;
    float* stage  = (float*)sbuf;

    if (bid >= NGROUPS) {
        // ======================= prep path =======================
        int base  = (bid - NGROUPS) * THREADS;
        int count = BN - base;
        if (count > THREADS) count = THREADS;

        int nfl = count * CC;
        for (int t = tid; t < nfl; t += THREADS)
            stage[t] = rcnn_cls[(size_t)base * CC + t];
        __syncthreads();

        if (tid < count) {
            int idx = base + tid;

            float* o_round = out;
            float* o_sig   = out + BN * 4;
            float* o_boxes = out + BN * 5;

            float4 r = ((const float4*)nms_reg)[idx];
            float q0 = __fdiv_rn(floorf(__fmul_rn(r.x, red)), red);
            float q1 = __fdiv_rn(floorf(__fmul_rn(r.y, red)), red);
            float q2 = __fdiv_rn(ceilf(__fmul_rn(r.z, red)), red);
            float q3 = __fdiv_rn(ceilf(__fmul_rn(r.w, red)), red);
            ((float4*)o_round)[idx] = make_float4(q0, q1, q2, q3);

            float4 rg = ((const float4*)rcnn_reg)[idx];
            ((float4*)o_boxes)[idx] = make_float4(
                __fadd_rn(rg.x, q0), __fadd_rn(rg.y, q1),
                __fadd_rn(rg.z, q2), __fadd_rn(rg.w, q3));

            float s = nms_cls[idx];
            o_sig[idx] = 1.0f / (1.0f + expf(-s));

            float* L = stage + tid * CC;
            // pass 1: max
            float m = -INFINITY;
            #pragma unroll
            for (int c = 0; c < CC; c++) m = fmaxf(m, L[c]);
            // pass 2: sum of exp (reference order)
            float sum = 0.0f;
            #pragma unroll
            for (int c = 0; c < CC; c++) sum += expf(L[c] - m);
            float inv = __fdiv_rn(1.0f, sum);
            // pass 3: probs (overwrite own slots) + first-max argmax
            int   am   = 0;
            float best = -INFINITY;
            #pragma unroll
            for (int c = 0; c < CC; c++) {
                float p = __fmul_rn(expf(L[c] - m), inv);
                L[c] = p;
                if (p > best) { best = p; am = c; }
            }
            // prep owns keep for amax==0 boxes (reference never keeps them)
            if (am == 0) o_keep[idx] = 0.0f;
        }
        __syncthreads();
        {
            float* o_probs = out + BN * 9;
            for (int t = tid; t < nfl; t += THREADS)
                o_probs[(size_t)base * CC + t] = stage[t];
        }
        return;
    }

    // ======================= group path =======================
    int b   = bid / (CC - 1);
    int cls = 1 + bid % (CC - 1);

    if (tid == 0) s_count = 0;
    __syncthreads();

    // gather: tiled, coalesced logit staging; conflict-free stride-21 LDS
    for (int tile = 0; tile < NTILES; tile++) {
        int tbase = tile * TILE;
        int tcnt  = NN - tbase;
        if (tcnt > TILE) tcnt = TILE;

        int nfl = tcnt * CC;
        const float* src = rcnn_cls + ((size_t)b * NN + tbase) * CC;
        for (int t = tid; t < nfl; t += THREADS) stage[t] = src[t];
        __syncthreads();

        if (tid < tcnt) {
            const float* L = stage + tid * CC;
            float bestl = -INFINITY, second = -INFINITY;
            int am = 0;
            #pragma unroll
            for (int c = 0; c < CC; c++) {
                float v = L[c];
                if (v > bestl) { second = bestl; bestl = v; am = c; }
                else if (v > second) second = v;
            }
            bool cand;
            float score = 0.0f;
            if (bestl - second > 1e-5f) {
                // unique max: argmax(probs) == argmax(logits)
                cand = (am == cls);
                if (cand) {
                    float sum = 0.0f;
                    #pragma unroll
                    for (int c = 0; c < CC; c++) sum += expf(L[c] - bestl);
                    float inv = __fdiv_rn(1.0f, sum);
                    score = __fmul_rn(expf(L[cls] - bestl), inv);
                }
            } else {
                // near-tie: exact reference p sequence + first-max argmax
                float sum = 0.0f;
                #pragma unroll
                for (int c = 0; c < CC; c++) sum += expf(L[c] - bestl);
                float inv = __fdiv_rn(1.0f, sum);
                int amp = 0; float bp = -INFINITY;
                float sc = 0.0f;
                #pragma unroll
                for (int c = 0; c < CC; c++) {
                    float p = __fmul_rn(expf(L[c] - bestl), inv);
                    if (p > bp) { bp = p; amp = c; }
                    if (c == cls) sc = p;
                }
                cand = (amp == cls);
                score = sc;
            }
            if (cand) {
                int n = tbase + tid;
                int pos = atomicAdd(&s_count, 1);
                if (pos < MAXM) {
                    unsigned int sb = __float_as_uint(score);
                    keysbuf[pos] = ((unsigned long long)sb << 32)
                                 | (unsigned long long)(0xFFFFFFFFu - (unsigned)n);
                }
            }
        }
        __syncthreads();
    }

    int M = s_count;
    if (M == 0) return;

    if (M <= MAXM) {
        float4*       tlbr  = (float4*)sbuf;
        float*        area  = (float*)(sbuf + 5120);
        int*          sidx  = (int*)(sbuf + 6400);
        unsigned int* keptw = (unsigned int*)(sbuf + 7680);
        const int W = (M + 31) >> 5;

        // rank sort (keys unique -> deterministic descending order)
        unsigned long long myk[2]; int myrank[2]; int nown = 0;
        for (int i = tid; i < M; i += THREADS) {
            unsigned long long k = keysbuf[i];
            int r = 0;
            for (int j = 0; j < M; j++) r += (keysbuf[j] > k);
            myk[nown] = k; myrank[nown] = r; nown++;
        }
        __syncthreads();
        for (int q = 0; q < nown; q++) keysbuf[myrank[q]] = myk[q];
        __syncthreads();

        // stage sorted boxes (bit-exact recompute) + areas + indices
        for (int i = tid; i < M; i += THREADS) {
            int n = (int)(0xFFFFFFFFu - (unsigned)(keysbuf[i] & 0xFFFFFFFFu));
            sidx[i] = n;
            float4 v;
            load_box(nms_reg, rcnn_reg, red, b * NN + n, &v);
            tlbr[i] = v;
            area[i] = __fmul_rn(fmaxf(__fsub_rn(v.z, v.x), 0.0f),
                                fmaxf(__fsub_rn(v.w, v.y), 0.0f));
        }
        __syncthreads();

        // suppression matrix: thread owns (row i, word w); no atomics
        int ncells = M * W;
        for (int t = tid; t < ncells; t += THREADS) {
            int i = t / W;
            int w = t - i * W;
            int jbase = w << 5;
            unsigned int word = 0;
            if (jbase + 31 > i) {
                float4 bi = tlbr[i];
                float  ai = area[i];
                #pragma unroll 4
                for (int bit = 0; bit < 32; bit++) {
                    int j = jbase + bit;
                    if (j > i && j < M) {
                        float4 bj = tlbr[j];
                        float ih = fmaxf(__fsub_rn(fminf(bi.z, bj.z), fmaxf(bi.x, bj.x)), 0.0f);
                        float iw = fmaxf(__fsub_rn(fminf(bi.w, bj.w), fmaxf(bi.y, bj.y)), 0.0f);
                        float inter = __fmul_rn(ih, iw);
                        float uni   = __fsub_rn(__fadd_rn(ai, area[j]), inter);
                        float iou   = __fdiv_rn(inter, fmaxf(uni, 1e-9f));
                        if (iou > 0.5f) word |= (1u << bit);
                    }
                }
            }
            maskbuf[i * W + w] = word;
        }
        __syncthreads();

        // warp 0: branchless chunked greedy scan
        if (tid < 32) {
            unsigned int R = 0u, K = 0u;
            int ldslane = (lane < W) ? lane : (W - 1);
            unsigned int lanemask = (lane < W) ? 0xFFFFFFFFu : 0u;
            for (int c = 0; c < W; c++) {
                unsigned int curw = __shfl_sync(0xFFFFFFFFu, R, c);
                int ibase = c << 5;
                #pragma unroll 8
                for (int bit = 0; bit < 32; bit++) {
                    int i = ibase + bit;
                    unsigned int valid = (i < M) ? 0xFFFFFFFFu : 0u;
                    unsigned int keptm = (~(curw >> bit) & 1u) ? valid : 0u;
                    unsigned int mwc = maskbuf[i * W + c]       & valid;
                    unsigned int mwl = maskbuf[i * W + ldslane] & lanemask & valid;
                    curw |= (mwc & keptm);
                    R    |= (mwl & keptm);
                    K    |= ((lane == c) ? (keptm & (1u << bit)) : 0u);
                }
            }
            if (lane < W) keptw[lane] = K;
        }
        __syncthreads();

        // keep (0/1); in-batch index 0 never kept (reference scan quirk)
        for (int i = tid; i < M; i += THREADS) {
            int n = sidx[i];
            bool kept = (keptw[i >> 5] >> (i & 31)) & 1u;
            o_keep[b * NN + n] = (kept && n != 0) ? 1.0f : 0.0f;
        }
    } else {
        // -------- fallback (M > 320; statistically unreachable) --------
        unsigned long long* keys = (unsigned long long*)sbuf;   // cap 3072
        if (tid == 0) s_count = 0;
        __syncthreads();
        // re-gather, direct (slow) reads, exact reference logic
        for (int n = tid; n < NN; n += THREADS) {
            const float* lg = rcnn_cls + ((size_t)b * NN + n) * CC;
            float l[CC];
            float bestl = -INFINITY;
            #pragma unroll
            for (int c = 0; c < CC; c++) { l[c] = lg[c]; bestl = fmaxf(bestl, l[c]); }
            float sum = 0.0f;
            #pragma unroll
            for (int c = 0; c < CC; c++) sum += expf(l[c] - bestl);
            float inv = __fdiv_rn(1.0f, sum);
            int amp = 0; float bp = -INFINITY; float sc = 0.0f;
            #pragma unroll
            for (int c = 0; c < CC; c++) {
                float p = __fmul_rn(expf(l[c] - bestl), inv);
                if (p > bp) { bp = p; amp = c; }
                if (c == cls) sc = p;
            }
            if (amp == cls) {
                int pos = atomicAdd(&s_count, 1);
                unsigned int sb = __float_as_uint(sc);
                keys[pos] = ((unsigned long long)sb << 32)
                          | (unsigned long long)(0xFFFFFFFFu - (unsigned)n);
            }
        }
        __syncthreads();
        M = s_count;

        int P = 1;
        while (P < M) P <<= 1;
        for (int i = M + tid; i < P; i += THREADS) keys[i] = 0ULL;
        __syncthreads();
        for (int k = 2; k <= P; k <<= 1) {
            for (int j = k >> 1; j > 0; j >>= 1) {
                for (int i = tid; i < P; i += THREADS) {
                    int ixj = i ^ j;
                    if (ixj > i) {
                        unsigned long long a = keys[i];
                        unsigned long long c = keys[ixj];
                        bool dirDesc = ((i & k) == 0);
                        if ((a < c) == dirDesc) { keys[i] = c; keys[ixj] = a; }
                    }
                }
                __syncthreads();
            }
        }
        unsigned char* st = (unsigned char*)maskbuf;   // 0=alive 1=suppressed 2=kept
        for (int i = tid; i < M; i += THREADS) st[i] = 0;
        __syncthreads();
        for (int i = 0; i < M; i++) {
            if (st[i] == 0) {
                int ni = (int)(0xFFFFFFFFu - (unsigned)(keys[i] & 0xFFFFFFFFu));
                float4 vi; load_box(nms_reg, rcnn_reg, red, b * NN + ni, &vi);
                float ai = __fmul_rn(fmaxf(__fsub_rn(vi.z, vi.x), 0.0f),
                                     fmaxf(__fsub_rn(vi.w, vi.y), 0.0f));
                if (tid == 0) st[i] = 2;
                for (int j = i + 1 + tid; j < M; j += THREADS) {
                    if (st[j]) continue;
                    int nj = (int)(0xFFFFFFFFu - (unsigned)(keys[j] & 0xFFFFFFFFu));
                    float4 vj; load_box(nms_reg, rcnn_reg, red, b * NN + nj, &vj);
                    float aj = __fmul_rn(fmaxf(__fsub_rn(vj.z, vj.x), 0.0f),
                                         fmaxf(__fsub_rn(vj.w, vj.y), 0.0f));
                    float ih = fmaxf(__fsub_rn(fminf(vi.z, vj.z), fmaxf(vi.x, vj.x)), 0.0f);
                    float iw = fmaxf(__fsub_rn(fminf(vi.w, vj.w), fmaxf(vi.y, vj.y)), 0.0f);
                    float inter = __fmul_rn(ih, iw);
                    float uni   = __fsub_rn(__fadd_rn(ai, aj), inter);
                    float iou   = __fdiv_rn(inter, fmaxf(uni, 1e-9f));
                    if (iou > 0.5f) st[j] = 1;
                }
            }
            __syncthreads();
        }
        for (int i = tid; i < M; i += THREADS) {
            int n = (int)(0xFFFFFFFFu - (unsigned)(keys[i] & 0xFFFFFFFFu));
            o_keep[b * NN + n] = (st[i] == 2 && n != 0) ? 1.0f : 0.0f;
        }
    }
}

extern "C" void kernel_launch(void* const* d_in, const int* in_sizes, int n_in,
                              void* d_out, int out_size)
{
    const float* nms_reg  = (const float*)d_in[0];
    const float* nms_cls  = (const float*)d_in[1];
    const float* rcnn_reg = (const float*)d_in[2];
    const float* rcnn_cls = (const float*)d_in[3];
    const unsigned int* red = (const unsigned int*)d_in[4];
    float* out = (float*)d_out;

    fused_kernel<<<NBLK, THREADS>>>(nms_reg, nms_cls, rcnn_reg, rcnn_cls, red, out);
}

// round 11
// speedup vs baseline: 1.6434x; 1.6434x over previous
#include <cuda_runtime.h>
#include <math.h>

#define BB 4
#define NN 3000
#define CC 21
#define BN (BB*NN)

#define NGROUPS (BB*(CC-1))            // 80
#define THREADS 512
#define NWARPS  (THREADS/32)           // 16
#define WSTRIDE 672                    // 21*32 floats per warp staging
#define PREP_BLOCKS ((BN + THREADS - 1) / THREADS)   // 24
#define NBLK (NGROUPS + PREP_BLOCKS)   // 104
#define NWTILES ((NN + 31) / 32)       // 94 warp-tiles per batch scan
#define MAXM  320
#define WMAX  10

// out layout (float32): [rounded BN*4][sigmoid BN][boxes BN*4][probs BN*C][keep BN]

// stagebuf (43008 B):
//   gather/prep phase: warp-private staging, warp w owns floats [w*672, (w+1)*672)
//   NMS phase overlay: maskbuf u32 [0,12800) | tlbr f4 [12800,17920)
//                      area f [17920,19200) | sidx i32 [19200,20480)
//                      keptw u32 [20480,20520)
//   fallback overlay:  keys u64 [0,32768) | st u8 [32768,35840)
__shared__ float              stagebuf[NWARPS * WSTRIDE];
__shared__ unsigned long long keysbuf[MAXM];
__shared__ int s_count;

__device__ __forceinline__ void load_box(const float* __restrict__ nms_reg,
                                         const float* __restrict__ rcnn_reg,
                                         float red, int gidx, float4* box)
{
    float4 r  = ((const float4*)nms_reg)[gidx];
    float4 rg = ((const float4*)rcnn_reg)[gidx];
    float q0 = __fdiv_rn(floorf(__fmul_rn(r.x, red)), red);
    float q1 = __fdiv_rn(floorf(__fmul_rn(r.y, red)), red);
    float q2 = __fdiv_rn(ceilf(__fmul_rn(r.z, red)), red);
    float q3 = __fdiv_rn(ceilf(__fmul_rn(r.w, red)), red);
    box->x = __fadd_rn(rg.x, q0);
    box->y = __fadd_rn(rg.y, q1);
    box->z = __fadd_rn(rg.z, q2);
    box->w = __fadd_rn(rg.w, q3);
}

__global__ void __launch_bounds__(THREADS)
fused_kernel(const float* __restrict__ nms_reg,
             const float* __restrict__ nms_cls,
             const float* __restrict__ rcnn_reg,
             const float* __restrict__ rcnn_cls,
             const unsigned int* __restrict__ red_raw,
             float* __restrict__ out)
{
    int tid  = threadIdx.x;
    int lane = tid & 31;
    int warp = tid >> 5;
    int bid  = blockIdx.x;

    unsigned int wr = red_raw[0];
    float red = (wr < 0x10000u) ? (float)wr : __uint_as_float(wr);

    float* o_keep = out + BN * 9 + BN * CC;

    if (bid >= NGROUPS) {
        // ======================= prep path =======================
        // warp-private staging: coalesced logit load, per-lane softmax,
        // coalesced probs write-back. No block barriers.
        int base = (bid - NGROUPS) * THREADS;
        int box0 = base + (warp << 5);
        int tcnt = BN - box0;
        if (tcnt > 32) tcnt = 32;
        if (tcnt <= 0) return;

        float* ws = stagebuf + warp * WSTRIDE;
        int nfl = tcnt * CC;
        const float* src = rcnn_cls + (size_t)box0 * CC;
        for (int k = lane; k < nfl; k += 32) ws[k] = src[k];
        __syncwarp();

        if (lane < tcnt) {
            int idx = box0 + lane;

            float* o_round = out;
            float* o_sig   = out + BN * 4;
            float* o_boxes = out + BN * 5;

            float4 r = ((const float4*)nms_reg)[idx];
            float q0 = __fdiv_rn(floorf(__fmul_rn(r.x, red)), red);
            float q1 = __fdiv_rn(floorf(__fmul_rn(r.y, red)), red);
            float q2 = __fdiv_rn(ceilf(__fmul_rn(r.z, red)), red);
            float q3 = __fdiv_rn(ceilf(__fmul_rn(r.w, red)), red);
            ((float4*)o_round)[idx] = make_float4(q0, q1, q2, q3);

            float4 rg = ((const float4*)rcnn_reg)[idx];
            ((float4*)o_boxes)[idx] = make_float4(
                __fadd_rn(rg.x, q0), __fadd_rn(rg.y, q1),
                __fadd_rn(rg.z, q2), __fadd_rn(rg.w, q3));

            float s = nms_cls[idx];
            o_sig[idx] = 1.0f / (1.0f + expf(-s));

            float* L = ws + lane * CC;
            float m = -INFINITY;
            #pragma unroll
            for (int c = 0; c < CC; c++) m = fmaxf(m, L[c]);
            float sum = 0.0f;
            #pragma unroll
            for (int c = 0; c < CC; c++) sum += expf(L[c] - m);
            float inv = __fdiv_rn(1.0f, sum);
            int   am   = 0;
            float best = -INFINITY;
            #pragma unroll
            for (int c = 0; c < CC; c++) {
                float p = __fmul_rn(expf(L[c] - m), inv);
                L[c] = p;                       // overwrite own slots
                if (p > best) { best = p; am = c; }
            }
            // prep owns keep for amax==0 boxes (reference never keeps them)
            if (am == 0) o_keep[idx] = 0.0f;
        }
        __syncwarp();
        {
            float* dst = out + BN * 9 + (size_t)box0 * CC;
            for (int k = lane; k < nfl; k += 32) dst[k] = ws[k];
        }
        return;
    }

    // ======================= group path =======================
    int b   = bid / (CC - 1);
    int cls = 1 + bid % (CC - 1);

    if (tid == 0) s_count = 0;
    __syncthreads();

    // gather via warp-private transpose: coalesced LDG + conflict-free LDS.
    for (int t = warp; t < NWTILES; t += NWARPS) {
        int box0 = t << 5;
        int tcnt = NN - box0;
        if (tcnt > 32) tcnt = 32;
        int nfl = tcnt * CC;
        const float* src = rcnn_cls + ((size_t)b * NN + box0) * CC;
        float* ws = stagebuf + warp * WSTRIDE;
        for (int k = lane; k < nfl; k += 32) ws[k] = src[k];
        __syncwarp();

        if (lane < tcnt) {
            const float* L = ws + lane * CC;
            float bestl = -INFINITY, second = -INFINITY;
            int am = 0;
            #pragma unroll
            for (int c = 0; c < CC; c++) {
                float v = L[c];
                if (v > bestl) { second = bestl; bestl = v; am = c; }
                else if (v > second) second = v;
            }
            bool cand;
            float score = 0.0f;
            if (bestl - second > 1e-5f) {
                // unique max: argmax(probs) == argmax(logits)
                cand = (am == cls);
                if (cand) {
                    float sum = 0.0f;
                    #pragma unroll
                    for (int c = 0; c < CC; c++) sum += expf(L[c] - bestl);
                    float inv = __fdiv_rn(1.0f, sum);
                    score = __fmul_rn(expf(L[cls] - bestl), inv);
                }
            } else {
                // near-tie: exact reference p sequence + first-max argmax
                float sum = 0.0f;
                #pragma unroll
                for (int c = 0; c < CC; c++) sum += expf(L[c] - bestl);
                float inv = __fdiv_rn(1.0f, sum);
                int amp = 0; float bp = -INFINITY; float sc = 0.0f;
                #pragma unroll
                for (int c = 0; c < CC; c++) {
                    float p = __fmul_rn(expf(L[c] - bestl), inv);
                    if (p > bp) { bp = p; amp = c; }
                    if (c == cls) sc = p;
                }
                cand = (amp == cls);
                score = sc;
            }
            if (cand) {
                int n = box0 + lane;
                int pos = atomicAdd(&s_count, 1);
                if (pos < MAXM) {
                    unsigned int sb = __float_as_uint(score);
                    keysbuf[pos] = ((unsigned long long)sb << 32)
                                 | (unsigned long long)(0xFFFFFFFFu - (unsigned)n);
                }
            }
        }
        __syncwarp();    // protect ws before next tile overwrites it
    }
    __syncthreads();

    int M = s_count;
    if (M == 0) return;

    unsigned char* nbuf = (unsigned char*)stagebuf;

    if (M <= MAXM) {
        unsigned int* maskb = (unsigned int*)nbuf;
        float4*       tlbr  = (float4*)(nbuf + 12800);
        float*        area  = (float*)(nbuf + 17920);
        int*          sidx  = (int*)(nbuf + 19200);
        unsigned int* keptw = (unsigned int*)(nbuf + 20480);
        const int W = (M + 31) >> 5;

        // rank sort (keys unique -> deterministic descending order)
        unsigned long long myk; int myrank = -1;
        if (tid < M) {
            myk = keysbuf[tid];
            int r = 0;
            for (int j = 0; j < M; j++) r += (keysbuf[j] > myk);
            myrank = r;
        }
        __syncthreads();
        if (myrank >= 0) keysbuf[myrank] = myk;
        __syncthreads();

        // stage sorted boxes (bit-exact recompute) + areas + indices
        if (tid < M) {
            int n = (int)(0xFFFFFFFFu - (unsigned)(keysbuf[tid] & 0xFFFFFFFFu));
            sidx[tid] = n;
            float4 v;
            load_box(nms_reg, rcnn_reg, red, b * NN + n, &v);
            tlbr[tid] = v;
            area[tid] = __fmul_rn(fmaxf(__fsub_rn(v.z, v.x), 0.0f),
                                  fmaxf(__fsub_rn(v.w, v.y), 0.0f));
        }
        __syncthreads();

        // suppression matrix: thread owns (row i, word w); no atomics
        int ncells = M * W;
        for (int t = tid; t < ncells; t += THREADS) {
            int i = t / W;
            int w = t - i * W;
            int jbase = w << 5;
            unsigned int word = 0;
            if (jbase + 31 > i) {
                float4 bi = tlbr[i];
                float  ai = area[i];
                #pragma unroll 4
                for (int bit = 0; bit < 32; bit++) {
                    int j = jbase + bit;
                    if (j > i && j < M) {
                        float4 bj = tlbr[j];
                        float ih = fmaxf(__fsub_rn(fminf(bi.z, bj.z), fmaxf(bi.x, bj.x)), 0.0f);
                        float iw = fmaxf(__fsub_rn(fminf(bi.w, bj.w), fmaxf(bi.y, bj.y)), 0.0f);
                        float inter = __fmul_rn(ih, iw);
                        float uni   = __fsub_rn(__fadd_rn(ai, area[j]), inter);
                        float iou   = __fdiv_rn(inter, fmaxf(uni, 1e-9f));
                        if (iou > 0.5f) word |= (1u << bit);
                    }
                }
            }
            maskb[i * W + w] = word;
        }
        __syncthreads();

        // warp 0: branchless chunked greedy scan
        if (tid < 32) {
            unsigned int R = 0u, K = 0u;
            int ldslane = (lane < W) ? lane : (W - 1);
            unsigned int lanemask = (lane < W) ? 0xFFFFFFFFu : 0u;
            for (int c = 0; c < W; c++) {
                unsigned int curw = __shfl_sync(0xFFFFFFFFu, R, c);
                int ibase = c << 5;
                #pragma unroll 8
                for (int bit = 0; bit < 32; bit++) {
                    int i = ibase + bit;
                    unsigned int valid = (i < M) ? 0xFFFFFFFFu : 0u;
                    unsigned int keptm = (~(curw >> bit) & 1u) ? valid : 0u;
                    unsigned int mwc = maskb[i * W + c]       & valid;
                    unsigned int mwl = maskb[i * W + ldslane] & lanemask & valid;
                    curw |= (mwc & keptm);
                    R    |= (mwl & keptm);
                    K    |= ((lane == c) ? (keptm & (1u << bit)) : 0u);
                }
            }
            if (lane < W) keptw[lane] = K;
        }
        __syncthreads();

        // keep (0/1); in-batch index 0 never kept (reference scan quirk)
        if (tid < M) {
            int n = sidx[tid];
            bool kept = (keptw[tid >> 5] >> (tid & 31)) & 1u;
            o_keep[b * NN + n] = (kept && n != 0) ? 1.0f : 0.0f;
        }
    } else {
        // -------- fallback (M > 320; statistically unreachable) --------
        unsigned long long* keys = (unsigned long long*)nbuf;     // cap 4096
        unsigned char*      st   = nbuf + 32768;                  // cap 3000+
        if (tid == 0) s_count = 0;
        __syncthreads();
        // re-gather with direct (slow) reads, exact reference logic
        for (int n = tid; n < NN; n += THREADS) {
            const float* lg = rcnn_cls + ((size_t)b * NN + n) * CC;
            float l[CC];
            float bestl = -INFINITY;
            #pragma unroll
            for (int c = 0; c < CC; c++) { l[c] = lg[c]; bestl = fmaxf(bestl, l[c]); }
            float sum = 0.0f;
            #pragma unroll
            for (int c = 0; c < CC; c++) sum += expf(l[c] - bestl);
            float inv = __fdiv_rn(1.0f, sum);
            int amp = 0; float bp = -INFINITY; float sc = 0.0f;
            #pragma unroll
            for (int c = 0; c < CC; c++) {
                float p = __fmul_rn(expf(l[c] - bestl), inv);
                if (p > bp) { bp = p; amp = c; }
                if (c == cls) sc = p;
            }
            if (amp == cls) {
                int pos = atomicAdd(&s_count, 1);
                unsigned int sb = __float_as_uint(sc);
                keys[pos] = ((unsigned long long)sb << 32)
                          | (unsigned long long)(0xFFFFFFFFu - (unsigned)n);
            }
        }
        __syncthreads();
        M = s_count;

        int P = 1;
        while (P < M) P <<= 1;
        for (int i = M + tid; i < P; i += THREADS) keys[i] = 0ULL;
        __syncthreads();
        for (int k = 2; k <= P; k <<= 1) {
            for (int j = k >> 1; j > 0; j >>= 1) {
                for (int i = tid; i < P; i += THREADS) {
                    int ixj = i ^ j;
                    if (ixj > i) {
                        unsigned long long a = keys[i];
                        unsigned long long c = keys[ixj];
                        bool dirDesc = ((i & k) == 0);
                        if ((a < c) == dirDesc) { keys[i] = c; keys[ixj] = a; }
                    }
                }
                __syncthreads();
            }
        }
        for (int i = tid; i < M; i += THREADS) st[i] = 0;   // 0=alive 1=supp 2=kept
        __syncthreads();
        for (int i = 0; i < M; i++) {
            if (st[i] == 0) {
                int ni = (int)(0xFFFFFFFFu - (unsigned)(keys[i] & 0xFFFFFFFFu));
                float4 vi; load_box(nms_reg, rcnn_reg, red, b * NN + ni, &vi);
                float ai = __fmul_rn(fmaxf(__fsub_rn(vi.z, vi.x), 0.0f),
                                     fmaxf(__fsub_rn(vi.w, vi.y), 0.0f));
                if (tid == 0) st[i] = 2;
                for (int j = i + 1 + tid; j < M; j += THREADS) {
                    if (st[j]) continue;
                    int nj = (int)(0xFFFFFFFFu - (unsigned)(keys[j] & 0xFFFFFFFFu));
                    float4 vj; load_box(nms_reg, rcnn_reg, red, b * NN + nj, &vj);
                    float aj = __fmul_rn(fmaxf(__fsub_rn(vj.z, vj.x), 0.0f),
                                         fmaxf(__fsub_rn(vj.w, vj.y), 0.0f));
                    float ih = fmaxf(__fsub_rn(fminf(vi.z, vj.z), fmaxf(vi.x, vj.x)), 0.0f);
                    float iw = fmaxf(__fsub_rn(fminf(vi.w, vj.w), fmaxf(vi.y, vj.y)), 0.0f);
                    float inter = __fmul_rn(ih, iw);
                    float uni   = __fsub_rn(__fadd_rn(ai, aj), inter);
                    float iou   = __fdiv_rn(inter, fmaxf(uni, 1e-9f));
                    if (iou > 0.5f) st[j] = 1;
                }
            }
            __syncthreads();
        }
        for (int i = tid; i < M; i += THREADS) {
            int n = (int)(0xFFFFFFFFu - (unsigned)(keys[i] & 0xFFFFFFFFu));
            o_keep[b * NN + n] = (st[i] == 2 && n != 0) ? 1.0f : 0.0f;
        }
    }
}

extern "C" void kernel_launch(void* const* d_in, const int* in_sizes, int n_in,
                              void* d_out, int out_size)
{
    const float* nms_reg  = (const float*)d_in[0];
    const float* nms_cls  = (const float*)d_in[1];
    const float* rcnn_reg = (const float*)d_in[2];
    const float* rcnn_cls = (const float*)d_in[3];
    const unsigned int* red = (const unsigned int*)d_in[4];
    float* out = (float*)d_out;

    fused_kernel<<<NBLK, THREADS>>>(nms_reg, nms_cls, rcnn_reg, rcnn_cls, red, out);
}